// round 15
// baseline (speedup 1.0000x reference)
#include <cuda_runtime.h>
#include <cuda_bf16.h>
#include <cstdint>

// DifferentiableNLMS: B=32, T=2000, F=513, L=32, mu=0.1, eps=1e-8
// ONE thread per (b,f) sequence (R13 core: no shuffles, packed f32x2, 16-pair
// ring, 2-step lookahead, packed (S|CC) prologue, EPS folded into seed).
// NEW: cp.async (LDGSTS) double-buffered SMEM staging for x/y. Loads have no
// register destinations, so DRAM latency is absorbed during the previous
// block's compute regardless of register pressure; consumption is cheap LDS
// from thread-private smem columns (bank = lane, conflict-free, no barrier).

#define NB 32
#define NT 2000
#define NF 513
#define NL 32
#define MU 0.1f
#define EPSV 1e-8f

#define NSEQ (NB * NF)         // 16416 sequences
#define NSTEP 16
#define NPB 8
#define NDBL 62                // 125 blocks: 62*2 in loop + block 124 peeled

typedef unsigned long long u64;

__device__ __forceinline__ u64 ffma2(u64 a, u64 b, u64 c) {
    u64 d; asm("fma.rn.f32x2 %0, %1, %2, %3;" : "=l"(d) : "l"(a), "l"(b), "l"(c));
    return d;
}
__device__ __forceinline__ u64 fadd2(u64 a, u64 b) {
    u64 d; asm("add.rn.f32x2 %0, %1, %2;" : "=l"(d) : "l"(a), "l"(b));
    return d;
}
__device__ __forceinline__ u64 pack2(float lo, float hi) {
    u64 d; asm("mov.b64 %0, {%1, %2};" : "=l"(d) : "f"(lo), "f"(hi));
    return d;
}
__device__ __forceinline__ void unpack2(u64 v, float& lo, float& hi) {
    asm("mov.b64 {%0, %1}, %2;" : "=f"(lo), "=f"(hi) : "l"(v));
}
__device__ __forceinline__ float negf(float x) {
    return __int_as_float(__float_as_int(x) ^ 0x80000000);
}
__device__ __forceinline__ void cpasync4(uint32_t dst, const float* src) {
    asm volatile("cp.async.ca.shared.global [%0], [%1], 4;" :: "r"(dst), "l"(src));
}
__device__ __forceinline__ void cp_commit() {
    asm volatile("cp.async.commit_group;");
}
template <int N>
__device__ __forceinline__ void cp_wait() {
    asm volatile("cp.async.wait_group %0;" :: "n"(N) : "memory");
}

#define ROWB (128 * 4)   // smem row stride in bytes (128 lanes * 4B)

// Stage block starting at t into smem stage (u32 base addrs for this thread).
__device__ __forceinline__ void stage_in(uint32_t ax, uint32_t ay,
                                         const float* __restrict__ xp,
                                         const float* __restrict__ yp, int t)
{
#pragma unroll
    for (int u = 0; u < NSTEP; u++) {
        cpasync4(ax + u * ROWB, xp + (size_t)(t + u) * NF);
        cpasync4(ay + u * ROWB, yp + (size_t)(t + u) * NF);
    }
    cp_commit();
}

// M0 = ring phase ((t0/2) mod 16): 0 or 8. Reads x/y from smem stage.
template <int M0>
__device__ __forceinline__ void run_block(
    u64 (&W2)[16], u64 (&P)[16], u64 (&Q)[16],
    u64& SC, float& xlast,
    const float (&sx)[NSTEP][128], const float (&sy)[NSTEP][128], int tid,
    float* __restrict__ ep, int t0, bool valid)
{
    // Pull staged x/y into registers (LDS, conflict-free, short lifetime).
    float xb[NSTEP], yb[NSTEP];
#pragma unroll
    for (int u = 0; u < NSTEP; u++) {
        xb[u] = sx[u][tid];
        yb[u] = sy[u][tid];
    }

    float minv[NSTEP];
    float ccs[NPB];
    float xm1_0 = xlast;

    // ---- Prologue: packed (S | CC) incremental chain, X-only ----
    {
        u64 sc = SC;
        float s0a[NPB], s1a[NPB], cca[NPB];
#pragma unroll
        for (int p = 0; p < NPB; p++) {
            const int m = (M0 + p) & 15;
            float a, b, bq, cq;
            unpack2(P[m], a, b);   // (x_{t-33}, x_{t-32})
            unpack2(Q[m], bq, cq); // (x_{t-32}, x_{t-31})
            float xm1 = p ? xb[2 * p - 1] : xm1_0;
            float x0 = xb[2 * p], x1 = xb[2 * p + 1];
            sc = ffma2(pack2(x0, xm1), pack2(x0, x0), sc);
            sc = ffma2(pack2(negf(b), negf(a)), pack2(b, b), sc);
            { float slo, shi; unpack2(sc, slo, shi); s0a[p] = slo; }
            sc = ffma2(pack2(x1, x0), pack2(x1, x1), sc);
            sc = ffma2(pack2(negf(cq), negf(bq)), pack2(cq, cq), sc);
            { float slo, shi; unpack2(sc, slo, shi); s1a[p] = slo; cca[p] = shi; }
        }
        SC = sc;
#pragma unroll
        for (int p = 0; p < NPB; p++) {
            minv[2 * p]     = __fdividef(MU, s0a[p]);  // EPS inside S seed
            minv[2 * p + 1] = __fdividef(MU, s1a[p]);
            ccs[p] = cca[p];
        }
    }
    xlast = xb[NSTEP - 1];

    // ---- Serial recursion: 2 steps per iteration ----
#pragma unroll
    for (int p = 0; p < NPB; p++) {
        const int m = (M0 + p) & 15;
        float xm1 = p ? xb[2 * p - 1] : xm1_0;
        float x0 = xb[2 * p], x1 = xb[2 * p + 1];
        P[m] = pack2(xm1, x0);
        Q[m] = pack2(x0, x1);

        u64 a0 = 0, a1 = 0, a2 = 0, a3 = 0;
        u64 b0 = 0, b1 = 0, b2 = 0, b3 = 0;
#pragma unroll
        for (int i = 0; i < 16; i += 4) {
            a0 = ffma2(W2[i + 0], P[(m + 1 + i) & 15], a0);
            a1 = ffma2(W2[i + 1], P[(m + 2 + i) & 15], a1);
            a2 = ffma2(W2[i + 2], P[(m + 3 + i) & 15], a2);
            a3 = ffma2(W2[i + 3], P[(m + 4 + i) & 15], a3);
            b0 = ffma2(W2[i + 0], Q[(m + 1 + i) & 15], b0);
            b1 = ffma2(W2[i + 1], Q[(m + 2 + i) & 15], b1);
            b2 = ffma2(W2[i + 2], Q[(m + 3 + i) & 15], b2);
            b3 = ffma2(W2[i + 3], Q[(m + 4 + i) & 15], b3);
        }
        u64 ap = fadd2(fadd2(a0, a1), fadd2(a2, a3));
        u64 aq = fadd2(fadd2(b0, b1), fadd2(b2, b3));
        float plo, phi, qlo, qhi;
        unpack2(ap, plo, phi);
        unpack2(aq, qlo, qhi);
        float pt = plo + phi;
        float qt = qlo + qhi;

        float e0 = yb[2 * p] - pt;
        float c0 = e0 * minv[2 * p];
        float e1 = fmaf(-c0, ccs[p], yb[2 * p + 1] - qt);
        float c1 = e1 * minv[2 * p + 1];

        if (valid) {
            ep[(size_t)(t0 + 2 * p) * NF] = e0;
            ep[(size_t)(t0 + 2 * p + 1) * NF] = e1;
        }

        u64 c0p = pack2(c0, c0);
        u64 c1p = pack2(c1, c1);
#pragma unroll
        for (int i = 0; i < 16; i++) {
            W2[i] = ffma2(c1p, Q[(m + 1 + i) & 15],
                          ffma2(c0p, P[(m + 1 + i) & 15], W2[i]));
        }
    }
}

__global__ void __launch_bounds__(128, 1)
nlms_kernel(const float* __restrict__ X, const float* __restrict__ Y,
            const float* __restrict__ Wp, float* __restrict__ out,
            int write_w)
{
    __shared__ float smx[2][NSTEP][128];
    __shared__ float smy[2][NSTEP][128];

    int tid = threadIdx.x;
    int gtid = blockIdx.x * blockDim.x + tid;
    bool valid = (gtid < NSEQ);
    int seq = valid ? gtid : (NSEQ - 1);   // clamp: no divergent exit
    int b = seq / NF;
    int f = seq - b * NF;

    size_t base = (size_t)b * NT * NF + f;
    const float* xp = X + base;
    const float* yp = Y + base;
    float* ep = out + base;                // E_hat_mag at offset 0

    // Per-thread smem column base addresses (u32 shared-space).
    uint32_t ax0 = (uint32_t)__cvta_generic_to_shared(&smx[0][0][tid]);
    uint32_t ax1 = (uint32_t)__cvta_generic_to_shared(&smx[1][0][tid]);
    uint32_t ay0 = (uint32_t)__cvta_generic_to_shared(&smy[0][0][tid]);
    uint32_t ay1 = (uint32_t)__cvta_generic_to_shared(&smy[1][0][tid]);

    u64 W2[16], P[16], Q[16];
#pragma unroll
    for (int i = 0; i < 16; i++) {
        float w0 = Wp[((size_t)b * NL + 2 * i) * NF + f];
        float w1 = Wp[((size_t)b * NL + 2 * i + 1) * NF + f];
        W2[i] = pack2(w0, w1);
        P[i] = 0;                          // zero pad: window starts empty
        Q[i] = 0;
    }
    u64 SC = pack2(EPSV, 0.f);             // lo = norm (+EPS), hi = lag-1 CC
    float xlast = 0.f;

    stage_in(ax0, ay0, xp, yp, 0);         // block 0 -> stage 0

    int t0 = 0;
#pragma unroll 1
    for (int dd = 0; dd < NDBL; dd++) {
        // even block 2dd -> stage 0; issue 2dd+1 into stage 1 first
        stage_in(ax1, ay1, xp, yp, t0 + NSTEP);
        cp_wait<1>();                      // stage 0 (current) complete
        run_block<0>(W2, P, Q, SC, xlast, smx[0], smy[0], tid, ep, t0, valid);
        t0 += NSTEP;
        // odd block 2dd+1 -> stage 1; issue 2dd+2 into stage 0 first
        stage_in(ax0, ay0, xp, yp, t0 + NSTEP);  // dd=61 issues block 124
        cp_wait<1>();                      // stage 1 (current) complete
        run_block<8>(W2, P, Q, SC, xlast, smx[1], smy[1], tid, ep, t0, valid);
        t0 += NSTEP;
    }
    cp_wait<0>();                          // block 124 (stage 0) complete
    run_block<0>(W2, P, Q, SC, xlast, smx[0], smy[0], tid, ep, t0, valid);

    if (write_w) {
        float* wf = out + (size_t)NB * NT * NF;  // W_final after E
#pragma unroll
        for (int i = 0; i < 16; i++) {
            float w0, w1;
            unpack2(W2[i], w0, w1);
            if (valid) {
                wf[((size_t)b * NL + 2 * i) * NF + f] = w0;
                wf[((size_t)b * NL + 2 * i + 1) * NF + f] = w1;
            }
        }
    }
}

extern "C" void kernel_launch(void* const* d_in, const int* in_sizes, int n_in,
                              void* d_out, int out_size)
{
    const float* X  = (const float*)d_in[0];  // X_hat_mag [B,T,F]
    const float* Y  = (const float*)d_in[1];  // Y_mag     [B,T,F]
    const float* Wp = (const float*)d_in[2];  // W_prev    [B,L,F]
    float* out = (float*)d_out;

    long long need = (long long)NB * NT * NF + (long long)NB * NL * NF;
    int write_w = ((long long)out_size >= need) ? 1 : 0;

    // 16416 sequences -> 129 blocks of 128 (96 clamped duplicates).
    // 1 block/SM, 1 warp/SMSP; warp loads 32 consecutive f (128B lines).
    nlms_kernel<<<129, 128>>>(X, Y, Wp, out, write_w);
}